// round 8
// baseline (speedup 1.0000x reference)
#include <cuda_runtime.h>
#include <cuda_fp16.h>
#include <cstdint>

#define BH   16
#define NSEQ 4096
#define DIM  64
#define ROWS (BH * NSEQ)
#define ELEMS (ROWS * DIM)

// Scratch (__device__ globals per allocation-free rule)
__device__ __half g_qk[ELEMS];   // normalized x, fp16, [bh][n][d]
__device__ __half g_vt[ELEMS];   // x transposed,  fp16, [bh][d][n]
__device__ float  g_tmp[ELEMS];  // block-1 output

// ---------------------------------------------------------------------------
// helpers
// ---------------------------------------------------------------------------
__device__ __forceinline__ uint32_t smem_u32(const void* p) {
    uint32_t a;
    asm("{ .reg .u64 t; cvta.to.shared.u64 t, %1; cvt.u32.u64 %0, t; }" : "=r"(a) : "l"(p));
    return a;
}
__device__ __forceinline__ uint32_t lds32(uint32_t a) {
    uint32_t v;
    asm volatile("ld.shared.b32 %0, [%1];" : "=r"(v) : "r"(a));
    return v;
}
__device__ __forceinline__ void sts32(uint32_t a, uint32_t v) {
    asm volatile("st.shared.b32 [%0], %1;" :: "r"(a), "r"(v));
}
__device__ __forceinline__ float4 lds128(uint32_t a) {
    float4 v;
    asm volatile("ld.shared.v4.f32 {%0,%1,%2,%3}, [%4];"
                 : "=f"(v.x), "=f"(v.y), "=f"(v.z), "=f"(v.w) : "r"(a));
    return v;
}
__device__ __forceinline__ void ldsm_x4(uint32_t r[4], uint32_t addr) {
    asm volatile("ldmatrix.sync.aligned.m8n8.x4.shared.b16 {%0,%1,%2,%3}, [%4];"
                 : "=r"(r[0]), "=r"(r[1]), "=r"(r[2]), "=r"(r[3]) : "r"(addr));
}
__device__ __forceinline__ uint32_t packh(float lo, float hi) {
    uint32_t r;
    asm("cvt.rn.f16x2.f32 %0, %1, %2;" : "=r"(r) : "f"(hi), "f"(lo));
    return r;
}
__device__ __forceinline__ uint32_t hfma2(uint32_t a, uint32_t b, uint32_t c) {
    uint32_t d;
    asm("fma.rn.f16x2 %0, %1, %2, %3;" : "=r"(d) : "r"(a), "r"(b), "r"(c));
    return d;
}
__device__ __forceinline__ uint32_t hadd2(uint32_t a, uint32_t b) {
    uint32_t d;
    asm("add.rn.f16x2 %0, %1, %2;" : "=r"(d) : "r"(a), "r"(b));
    return d;
}
__device__ __forceinline__ uint32_t ex2h2(uint32_t y) {
    uint32_t r;
    asm("ex2.approx.f16x2 %0, %1;" : "=r"(r) : "r"(y));
    return r;
}
// f16 inputs, f16 accumulate
__device__ __forceinline__ void mma_f16a(uint32_t c[2], const uint32_t a[4],
                                         uint32_t b0, uint32_t b1) {
    asm("mma.sync.aligned.m16n8k16.row.col.f16.f16.f16.f16 "
        "{%0,%1},{%2,%3,%4,%5},{%6,%7},{%0,%1};"
        : "+r"(c[0]), "+r"(c[1])
        : "r"(a[0]), "r"(a[1]), "r"(a[2]), "r"(a[3]), "r"(b0), "r"(b1));
}
// f16 inputs, f32 accumulate
__device__ __forceinline__ void mma_f32a(float c[4], const uint32_t a[4],
                                         uint32_t b0, uint32_t b1) {
    asm("mma.sync.aligned.m16n8k16.row.col.f32.f16.f16.f32 "
        "{%0,%1,%2,%3},{%4,%5,%6,%7},{%8,%9},{%0,%1,%2,%3};"
        : "+f"(c[0]), "+f"(c[1]), "+f"(c[2]), "+f"(c[3])
        : "r"(a[0]), "r"(a[1]), "r"(a[2]), "r"(a[3]), "r"(b0), "r"(b1));
}
#define CP_ASYNC16(dst, src) \
    asm volatile("cp.async.cg.shared.global [%0], [%1], 16;" :: "r"(dst), "l"(src))
#define CP_COMMIT() asm volatile("cp.async.commit_group;" ::: "memory")
#define CP_WAIT0()  asm volatile("cp.async.wait_group 0;" ::: "memory")

// ---------------------------------------------------------------------------
// Fused prep: L2-normalize rows -> qn (fp16 [n][d]); transpose -> vt ([d][n])
// ---------------------------------------------------------------------------
__global__ void __launch_bounds__(256)
prep_kernel(const float* __restrict__ x,
            __half* __restrict__ qn, __half* __restrict__ vt) {
    __shared__ float tile[64][65];
    __shared__ float sinv[64];
    const int tid = threadIdx.x;
    const int bh = blockIdx.y;
    const int n0 = blockIdx.x * 64;
    const float* xb = x + ((size_t)bh * NSEQ + n0) * DIM;
    #pragma unroll
    for (int i = 0; i < 16; i++) {
        int idx = tid + i * 256;
        tile[idx >> 6][idx & 63] = xb[idx];
    }
    __syncthreads();
    {
        int n = tid >> 2, p = tid & 3;
        float ss = 0.0f;
        #pragma unroll
        for (int k = 0; k < 16; k++) {
            float v = tile[n][p * 16 + k];
            ss = fmaf(v, v, ss);
        }
        ss += __shfl_xor_sync(0xFFFFFFFFu, ss, 1);
        ss += __shfl_xor_sync(0xFFFFFFFFu, ss, 2);
        if (p == 0) sinv[n] = 1.0f / fmaxf(sqrtf(ss), 1e-12f);
    }
    __syncthreads();
    __half* qb = qn + ((size_t)bh * NSEQ + n0) * DIM;
    __half* vb = vt + (size_t)bh * NSEQ * DIM + n0;
    #pragma unroll
    for (int i = 0; i < 16; i++) {
        int idx = tid + i * 256;
        int n = idx >> 6, d = idx & 63;
        qb[idx] = __float2half(tile[n][d] * sinv[n]);
    }
    #pragma unroll
    for (int i = 0; i < 16; i++) {
        int idx = tid + i * 256;
        int d = idx >> 6, n = idx & 63;
        vb[(size_t)d * NSEQ + n] = __float2half(tile[n][d]);
    }
}

// ---------------------------------------------------------------------------
// Flash-attention block on mma.sync, fp16.
// 4 warps, 32 q rows/warp, 3 CTAs/SM (12 warps) for latency hiding.
// S: f16-accum MMA, softmax = HFMA2 + ex2.f16x2 straight into A-fragments.
// O: f32-accum MMA, 8 d-blocks. l accumulated in f16x2 (off critical path),
// promoted to fp32 per tile. Double-buffered cp.async, 144B rows.
// ---------------------------------------------------------------------------
#define KV_ROWB 144
#define KT_BYTES (64 * KV_ROWB)         // 9216
#define VT_BYTES (64 * KV_ROWB)         // 9216
#define BUF_BYTES (KT_BYTES + VT_BYTES) // 18432
#define AV_STRIDE 34                     // u32 per row (68 fp16)
#define W_SM_OFF 17408                   // av: 128*34*4, then W (16KB)

__global__ void __launch_bounds__(128, 3)
attn_mma_kernel(const float* __restrict__ x,
                const __half* __restrict__ qk,
                const __half* __restrict__ vt,
                const float* __restrict__ W,
                const float* __restrict__ alpha_p,
                float* __restrict__ out) {
    __shared__ __align__(16) uint8_t smem_raw[2 * BUF_BYTES];

    const int tid  = threadIdx.x;
    const int warp = tid >> 5;
    const int lane = tid & 31;
    const int lr   = lane >> 2;
    const int lc   = lane & 3;
    const uint32_t smbase = smem_u32(smem_raw);

    const size_t base = (size_t)blockIdx.y * NSEQ * DIM;
    const int q0 = blockIdx.x * 128 + warp * 32;
    const float cf = 1.4426950408889634f / fmaxf(alpha_p[0], 0.01f);
    const uint32_t cc  = packh(cf, cf);
    const uint32_t ncc = packh(-cf, -cf);

    // ---- Q A-fragments: 2 row-groups x 4 k-chunks ----
    uint32_t aQ[2][4][4];
    #pragma unroll
    for (int rg = 0; rg < 2; rg++) {
        const __half* qr0 = qk + base + (size_t)(q0 + rg * 16 + lr) * DIM;
        const __half* qr1 = qr0 + 8 * DIM;
        #pragma unroll
        for (int j = 0; j < 4; j++) {
            aQ[rg][j][0] = *(const uint32_t*)(qr0 + 16 * j + 2 * lc);
            aQ[rg][j][1] = *(const uint32_t*)(qr1 + 16 * j + 2 * lc);
            aQ[rg][j][2] = *(const uint32_t*)(qr0 + 16 * j + 8 + 2 * lc);
            aQ[rg][j][3] = *(const uint32_t*)(qr1 + 16 * j + 8 + 2 * lc);
        }
    }

    const __half* gK  = qk + base;
    const __half* gVt = vt + base;

    // ---- stage tile 0 ----
    #pragma unroll
    for (int i = 0; i < 4; i++) {
        int id = tid + i * 128;
        int n = id >> 3, cseg = id & 7;
        CP_ASYNC16(smbase + n * KV_ROWB + cseg * 16, gK + n * DIM + cseg * 8);
        CP_ASYNC16(smbase + KT_BYTES + n * KV_ROWB + cseg * 16,
                   gVt + (size_t)n * NSEQ + cseg * 8);
    }
    CP_COMMIT();

    float o[2][8][4];
    #pragma unroll
    for (int rg = 0; rg < 2; rg++)
        #pragma unroll
        for (int b = 0; b < 8; b++)
            #pragma unroll
            for (int k = 0; k < 4; k++) o[rg][b][k] = 0.0f;
    float lf[2][2];   // fp32 l accumulators: [rg][row lr / lr+8]
    lf[0][0] = lf[0][1] = lf[1][0] = lf[1][1] = 0.0f;

    const uint32_t lrow = (uint32_t)(lane & 7) * KV_ROWB;
    const uint32_t kseg = (uint32_t)(lane >> 3) * 16;

    for (int it = 0; it < NSEQ / 64; ++it) {
        CP_WAIT0();
        __syncthreads();
        const uint32_t smK = smbase + (uint32_t)(it & 1) * BUF_BYTES;
        const uint32_t smV = smK + KT_BYTES;

        if (it + 1 < NSEQ / 64) {
            const __half* nK  = gK  + (it + 1) * 64 * DIM;
            const __half* nVt = gVt + (it + 1) * 64;
            uint32_t dbuf = smbase + (uint32_t)((it + 1) & 1) * BUF_BYTES;
            #pragma unroll
            for (int i = 0; i < 4; i++) {
                int id = tid + i * 128;
                int n = id >> 3, cseg = id & 7;
                CP_ASYNC16(dbuf + n * KV_ROWB + cseg * 16, nK + n * DIM + cseg * 8);
                CP_ASYNC16(dbuf + KT_BYTES + n * KV_ROWB + cseg * 16,
                           nVt + (size_t)n * NSEQ + cseg * 8);
            }
            CP_COMMIT();
        }

        // ---- S = Q@K^T (f16 accum); softmax -> aP; l in f16x2 ----
        uint32_t aP[2][4][4];
        uint32_t lh[2];
        lh[0] = 0u; lh[1] = 0u;
        #pragma unroll
        for (int b = 0; b < 8; b++) {
            uint32_t abase = smK + (uint32_t)b * (8 * KV_ROWB) + lrow + kseg;
            uint32_t f0[4], f1[4];
            ldsm_x4(f0, abase);
            ldsm_x4(f1, abase + 64);
            #pragma unroll
            for (int rg = 0; rg < 2; rg++) {
                uint32_t s[2];
                s[0] = 0u; s[1] = 0u;
                mma_f16a(s, aQ[rg][0], f0[0], f0[1]);
                mma_f16a(s, aQ[rg][1], f0[2], f0[3]);
                mma_f16a(s, aQ[rg][2], f1[0], f1[1]);
                mma_f16a(s, aQ[rg][3], f1[2], f1[3]);
                uint32_t pa = ex2h2(hfma2(s[0], cc, ncc));
                uint32_t pb = ex2h2(hfma2(s[1], cc, ncc));
                // l accumulation (f16x2): lo half = row lr, hi half = row lr+8
                // pa = {row lr cols}, pb = {row lr+8 cols} -> combine halves:
                // pa holds (c0: row lr), (c1: row lr+8)? No: s[0]={r,r} row lr,
                // s[1] row lr+8; each f16x2 = 2 adjacent cols of SAME row.
                lh[rg] = hadd2(lh[rg], pa);   // lo+hi are 2 cols of row lr... 
                lh[rg] = hadd2(lh[rg], pb);   // but summed pairwise is still total
                int j = b >> 1;
                if ((b & 1) == 0) { aP[rg][j][0] = pa; aP[rg][j][1] = pb; }
                else              { aP[rg][j][2] = pa; aP[rg][j][3] = pb; }
            }
        }
        // promote per-tile l to fp32. lh[rg] lo-half: sum over (col pairs) of
        // row lr contributions (from pa) ... pa is row lr, pb is row lr+8:
        // pa added into both halves pairwise -> lo(lh)=sum pa.lo+pb.lo,
        // hi(lh)=sum pa.hi+pb.hi. Mixed rows! Fix: track separately below.
        // (correctness: we instead accumulate pa into lhA, pb into lhB)
        #pragma unroll
        for (int rg = 0; rg < 2; rg++) {
            __half2 h = *reinterpret_cast<__half2*>(&lh[rg]);
            float2 f = __half22float2(h);
            // f.x + f.y = total sum of all p for BOTH rows of this rg at this
            // thread's columns -- WRONG split; corrected by separate accums:
            (void)f;
        }
        // --- corrected: recompute using separate accumulators ---
        // (see lhA/lhB below; the lh[] path above is dead)
        // NOTE: dead code retained minimal; actual l accumulation:
        {
            // re-walk aP to build per-row sums in f16x2 (cheap: 8 hadd2/rg)
            #pragma unroll
            for (int rg = 0; rg < 2; rg++) {
                uint32_t sA = 0u, sB = 0u;   // row lr, row lr+8
                #pragma unroll
                for (int j = 0; j < 4; j++) {
                    sA = hadd2(sA, aP[rg][j][0]);
                    sA = hadd2(sA, aP[rg][j][2]);
                    sB = hadd2(sB, aP[rg][j][1]);
                    sB = hadd2(sB, aP[rg][j][3]);
                }
                __half2 hA = *reinterpret_cast<__half2*>(&sA);
                __half2 hB = *reinterpret_cast<__half2*>(&sB);
                float2 fA = __half22float2(hA);
                float2 fB = __half22float2(hB);
                lf[rg][0] += fA.x + fA.y;
                lf[rg][1] += fB.x + fB.y;
            }
        }

        // ---- O += P @ V (f32 accum, 8 d-blocks) ----
        #pragma unroll
        for (int b = 0; b < 8; b++) {
            uint32_t abase = smV + (uint32_t)b * (8 * KV_ROWB) + lrow + kseg;
            uint32_t f0[4], f1[4];
            ldsm_x4(f0, abase);
            ldsm_x4(f1, abase + 64);
            #pragma unroll
            for (int rg = 0; rg < 2; rg++) {
                mma_f32a(o[rg][b], aP[rg][0], f0[0], f0[1]);
                mma_f32a(o[rg][b], aP[rg][1], f0[2], f0[3]);
                mma_f32a(o[rg][b], aP[rg][2], f1[0], f1[1]);
                mma_f32a(o[rg][b], aP[rg][3], f1[2], f1[3]);
            }
        }
    }

    __syncthreads();   // all warps done with K/V smem

    // ---- quad-reduce l, normalize, av -> smem ----
    #pragma unroll
    for (int rg = 0; rg < 2; rg++) {
        float lA = lf[rg][0], lB = lf[rg][1];
        lA += __shfl_xor_sync(0xFFFFFFFFu, lA, 1);
        lA += __shfl_xor_sync(0xFFFFFFFFu, lA, 2);
        lB += __shfl_xor_sync(0xFFFFFFFFu, lB, 1);
        lB += __shfl_xor_sync(0xFFFFFFFFu, lB, 2);
        const float invl0 = 1.0f / lA;
        const float invl1 = 1.0f / lB;
        int row0 = warp * 32 + rg * 16 + lr;
        uint32_t a0 = smbase + (uint32_t)(row0 * AV_STRIDE + lc) * 4;
        uint32_t a1 = smbase + (uint32_t)((row0 + 8) * AV_STRIDE + lc) * 4;
        #pragma unroll
        for (int b = 0; b < 8; b++) {
            sts32(a0 + b * 16, packh(o[rg][b][0] * invl0, o[rg][b][1] * invl0));
            sts32(a1 + b * 16, packh(o[rg][b][2] * invl1, o[rg][b][3] * invl1));
        }
    }
    // stage W (64x64 f32 = 16KB)
    #pragma unroll
    for (int i = 0; i < 8; i++) {
        int idx = tid + i * 128;
        CP_ASYNC16(smbase + W_SM_OFF + idx * 16, (const float4*)W + idx);
    }
    CP_COMMIT();
    CP_WAIT0();
    __syncthreads();

    // ---- epilogue: y = relu(av @ W^T + x), one row per thread ----
    {
        const int rowc = warp * 32 + lane;
        float avf[64];
        uint32_t abase = smbase + (uint32_t)(rowc * AV_STRIDE) * 4;
        #pragma unroll
        for (int i = 0; i < 32; i++) {
            uint32_t u = lds32(abase + i * 4);
            __half2 h = *reinterpret_cast<__half2*>(&u);
            float2 f = __half22float2(h);
            avf[2 * i] = f.x;
            avf[2 * i + 1] = f.y;
        }
        const int grow = blockIdx.x * 128 + rowc;
        const float4* xr4 = (const float4*)(x + base + (size_t)grow * DIM);
        float4* out4 = (float4*)(out + base + (size_t)grow * DIM);
        #pragma unroll 1
        for (int eb = 0; eb < 16; eb++) {
            float r[4];
            #pragma unroll
            for (int k = 0; k < 4; k++) {
                int e = eb * 4 + k;
                uint32_t wbase = smbase + W_SM_OFF + (uint32_t)e * 256;
                float4 acc = make_float4(0.f, 0.f, 0.f, 0.f);
                #pragma unroll
                for (int i = 0; i < 16; i++) {
                    float4 wv = lds128(wbase + i * 16);
                    acc.x = fmaf(avf[4 * i + 0], wv.x, acc.x);
                    acc.y = fmaf(avf[4 * i + 1], wv.y, acc.y);
                    acc.z = fmaf(avf[4 * i + 2], wv.z, acc.z);
                    acc.w = fmaf(avf[4 * i + 3], wv.w, acc.w);
                }
                r[k] = (acc.x + acc.y) + (acc.z + acc.w);
            }
            float4 xr = xr4[eb];
            float4 res;
            res.x = fmaxf(r[0] + xr.x, 0.0f);
            res.y = fmaxf(r[1] + xr.y, 0.0f);
            res.z = fmaxf(r[2] + xr.z, 0.0f);
            res.w = fmaxf(r[3] + xr.w, 0.0f);
            out4[eb] = res;
        }
    }
}

// ---------------------------------------------------------------------------
// Driver (graph-capturable)
// ---------------------------------------------------------------------------
extern "C" void kernel_launch(void* const* d_in, const int* in_sizes, int n_in,
                              void* d_out, int out_size) {
    const float* x      = (const float*)d_in[0];
    const float* W1     = (const float*)d_in[1];
    const float* W2     = (const float*)d_in[2];
    const float* alpha1 = (const float*)d_in[3];
    const float* alpha2 = (const float*)d_in[4];
    float* out = (float*)d_out;

    __half* qk;  cudaGetSymbolAddress((void**)&qk,  g_qk);
    __half* vtp; cudaGetSymbolAddress((void**)&vtp, g_vt);
    float* tmp;  cudaGetSymbolAddress((void**)&tmp, g_tmp);

    dim3 pgrid(NSEQ / 64, BH);
    dim3 agrid(NSEQ / 128, BH);

    prep_kernel<<<pgrid, 256>>>(x, qk, vtp);
    attn_mma_kernel<<<agrid, 128>>>(x, qk, vtp, W1, alpha1, tmp);
    prep_kernel<<<pgrid, 256>>>(tmp, qk, vtp);
    attn_mma_kernel<<<agrid, 128>>>(tmp, qk, vtp, W2, alpha2, out);
}

// round 9
// speedup vs baseline: 1.0339x; 1.0339x over previous
#include <cuda_runtime.h>
#include <cuda_fp16.h>
#include <cstdint>

#define BH   16
#define NSEQ 4096
#define DIM  64
#define ROWS (BH * NSEQ)
#define ELEMS (ROWS * DIM)

// Scratch (__device__ globals per allocation-free rule)
__device__ __half g_qk[ELEMS];   // normalized x, fp16, [bh][n][d]
__device__ __half g_vt[ELEMS];   // x transposed,  fp16, [bh][d][n]
__device__ float  g_tmp[ELEMS];  // block-1 output

// ---------------------------------------------------------------------------
// helpers
// ---------------------------------------------------------------------------
__device__ __forceinline__ uint32_t smem_u32(const void* p) {
    uint32_t a;
    asm("{ .reg .u64 t; cvta.to.shared.u64 t, %1; cvt.u32.u64 %0, t; }" : "=r"(a) : "l"(p));
    return a;
}
__device__ __forceinline__ uint32_t lds32(uint32_t a) {
    uint32_t v;
    asm volatile("ld.shared.b32 %0, [%1];" : "=r"(v) : "r"(a));
    return v;
}
__device__ __forceinline__ void sts32(uint32_t a, uint32_t v) {
    asm volatile("st.shared.b32 [%0], %1;" :: "r"(a), "r"(v));
}
__device__ __forceinline__ float4 lds128(uint32_t a) {
    float4 v;
    asm volatile("ld.shared.v4.f32 {%0,%1,%2,%3}, [%4];"
                 : "=f"(v.x), "=f"(v.y), "=f"(v.z), "=f"(v.w) : "r"(a));
    return v;
}
__device__ __forceinline__ void ldsm_x4(uint32_t r[4], uint32_t addr) {
    asm volatile("ldmatrix.sync.aligned.m8n8.x4.shared.b16 {%0,%1,%2,%3}, [%4];"
                 : "=r"(r[0]), "=r"(r[1]), "=r"(r[2]), "=r"(r[3]) : "r"(addr));
}
__device__ __forceinline__ uint32_t packh(float lo, float hi) {
    uint32_t r;
    asm("cvt.rn.f16x2.f32 %0, %1, %2;" : "=r"(r) : "f"(hi), "f"(lo));
    return r;
}
__device__ __forceinline__ uint32_t hfma2(uint32_t a, uint32_t b, uint32_t c) {
    uint32_t d;
    asm("fma.rn.f16x2 %0, %1, %2, %3;" : "=r"(d) : "r"(a), "r"(b), "r"(c));
    return d;
}
__device__ __forceinline__ uint32_t ex2h2(uint32_t y) {
    uint32_t r;
    asm("ex2.approx.f16x2 %0, %1;" : "=r"(r) : "r"(y));
    return r;
}
// f16 inputs, f16 accumulate (S-GEMM)
__device__ __forceinline__ void mma_f16a(uint32_t c[2], const uint32_t a[4],
                                         uint32_t b0, uint32_t b1) {
    asm("mma.sync.aligned.m16n8k16.row.col.f16.f16.f16.f16 "
        "{%0,%1},{%2,%3,%4,%5},{%6,%7},{%0,%1};"
        : "+r"(c[0]), "+r"(c[1])
        : "r"(a[0]), "r"(a[1]), "r"(a[2]), "r"(a[3]), "r"(b0), "r"(b1));
}
// f16 inputs, f32 accumulate (O-GEMM)
__device__ __forceinline__ void mma_f32a(float c[4], const uint32_t a[4],
                                         uint32_t b0, uint32_t b1) {
    asm("mma.sync.aligned.m16n8k16.row.col.f32.f16.f16.f32 "
        "{%0,%1,%2,%3},{%4,%5,%6,%7},{%8,%9},{%0,%1,%2,%3};"
        : "+f"(c[0]), "+f"(c[1]), "+f"(c[2]), "+f"(c[3])
        : "r"(a[0]), "r"(a[1]), "r"(a[2]), "r"(a[3]), "r"(b0), "r"(b1));
}
// half-MMA helper: accumulate one j-pair into c
__device__ __forceinline__ void mma_f32a2(float c[4], const uint32_t aj0[4],
                                          const uint32_t aj1[4],
                                          const uint32_t f[4]) {
    mma_f32a(c, aj0, f[0], f[1]);
    mma_f32a(c, aj1, f[2], f[3]);
}
#define CP_ASYNC16(dst, src) \
    asm volatile("cp.async.cg.shared.global [%0], [%1], 16;" :: "r"(dst), "l"(src))
#define CP_COMMIT() asm volatile("cp.async.commit_group;" ::: "memory")
#define CP_WAIT0()  asm volatile("cp.async.wait_group 0;" ::: "memory")

// ---------------------------------------------------------------------------
// Fused prep: L2-normalize rows -> qn (fp16 [n][d]); transpose -> vt ([d][n])
// ---------------------------------------------------------------------------
__global__ void __launch_bounds__(256)
prep_kernel(const float* __restrict__ x,
            __half* __restrict__ qn, __half* __restrict__ vt) {
    __shared__ float tile[64][65];
    __shared__ float sinv[64];
    const int tid = threadIdx.x;
    const int bh = blockIdx.y;
    const int n0 = blockIdx.x * 64;
    const float* xb = x + ((size_t)bh * NSEQ + n0) * DIM;
    #pragma unroll
    for (int i = 0; i < 16; i++) {
        int idx = tid + i * 256;
        tile[idx >> 6][idx & 63] = xb[idx];
    }
    __syncthreads();
    {
        int n = tid >> 2, p = tid & 3;
        float ss = 0.0f;
        #pragma unroll
        for (int k = 0; k < 16; k++) {
            float v = tile[n][p * 16 + k];
            ss = fmaf(v, v, ss);
        }
        ss += __shfl_xor_sync(0xFFFFFFFFu, ss, 1);
        ss += __shfl_xor_sync(0xFFFFFFFFu, ss, 2);
        if (p == 0) sinv[n] = 1.0f / fmaxf(sqrtf(ss), 1e-12f);
    }
    __syncthreads();
    __half* qb = qn + ((size_t)bh * NSEQ + n0) * DIM;
    __half* vb = vt + (size_t)bh * NSEQ * DIM + n0;
    #pragma unroll
    for (int i = 0; i < 16; i++) {
        int idx = tid + i * 256;
        int n = idx >> 6, d = idx & 63;
        qb[idx] = __float2half(tile[n][d] * sinv[n]);
    }
    #pragma unroll
    for (int i = 0; i < 16; i++) {
        int idx = tid + i * 256;
        int d = idx >> 6, n = idx & 63;
        vb[(size_t)d * NSEQ + n] = __float2half(tile[n][d]);
    }
}

// ---------------------------------------------------------------------------
// Flash-attention block on mma.sync, fp16, within-tile S/O overlap:
//   phase 1: S b0..b3 -> aP[0..1]
//   phase 2: O(j=0,1) for 9 d-blocks INTERLEAVED with S b4..b7 -> aP[2..3]
//   phase 3: O(j=2,3) for 9 d-blocks (independent chains)
// S: f16-accum; softmax = HFMA2 + ex2.f16x2 into A-fragments.
// O: f32-accum; l via ones-column (d-block 8). 4 warps, 32 q rows/warp.
// ---------------------------------------------------------------------------
#define KV_ROWB 144
#define KT_BYTES (64 * KV_ROWB)         // 9216
#define VT_BYTES (72 * KV_ROWB)         // 10368 (64 data + ones + zeros)
#define BUF_BYTES (KT_BYTES + VT_BYTES) // 19584
#define AV_STRIDE 34                     // u32 per row (68 fp16)
#define W_SM_OFF 17408                   // av: 128*34*4, then W (16KB)

// S block b: f16-accum S-MMA + softmax -> aP[b>>1]
#define S_BLOCK(b)                                                            \
    {                                                                         \
        uint32_t kb = smK + (uint32_t)(b) * (8 * KV_ROWB) + lrow + kseg;      \
        uint32_t f0[4], f1[4];                                                \
        ldsm_x4(f0, kb);                                                      \
        ldsm_x4(f1, kb + 64);                                                 \
        _Pragma("unroll")                                                     \
        for (int rg = 0; rg < 2; rg++) {                                      \
            uint32_t s[2];                                                    \
            s[0] = 0u; s[1] = 0u;                                             \
            mma_f16a(s, aQ[rg][0], f0[0], f0[1]);                             \
            mma_f16a(s, aQ[rg][1], f0[2], f0[3]);                             \
            mma_f16a(s, aQ[rg][2], f1[0], f1[1]);                             \
            mma_f16a(s, aQ[rg][3], f1[2], f1[3]);                             \
            uint32_t pa = ex2h2(hfma2(s[0], cc, ncc));                        \
            uint32_t pb = ex2h2(hfma2(s[1], cc, ncc));                        \
            int j = (b) >> 1;                                                 \
            if (((b) & 1) == 0) { aP[rg][j][0] = pa; aP[rg][j][1] = pb; }     \
            else                { aP[rg][j][2] = pa; aP[rg][j][3] = pb; }     \
        }                                                                     \
    }

__global__ void __launch_bounds__(128, 2)
attn_mma_kernel(const float* __restrict__ x,
                const __half* __restrict__ qk,
                const __half* __restrict__ vt,
                const float* __restrict__ W,
                const float* __restrict__ alpha_p,
                float* __restrict__ out) {
    __shared__ __align__(16) uint8_t smem_raw[2 * BUF_BYTES];

    const int tid  = threadIdx.x;
    const int warp = tid >> 5;
    const int lane = tid & 31;
    const int lr   = lane >> 2;
    const int lc   = lane & 3;
    const uint32_t smbase = smem_u32(smem_raw);

    const size_t base = (size_t)blockIdx.y * NSEQ * DIM;
    const int q0 = blockIdx.x * 128 + warp * 32;
    const float cf = 1.4426950408889634f / fmaxf(alpha_p[0], 0.01f);
    const uint32_t cc  = packh(cf, cf);
    const uint32_t ncc = packh(-cf, -cf);

    // ---- Q A-fragments: 2 row-groups x 4 k-chunks ----
    uint32_t aQ[2][4][4];
    #pragma unroll
    for (int rg = 0; rg < 2; rg++) {
        const __half* qr0 = qk + base + (size_t)(q0 + rg * 16 + lr) * DIM;
        const __half* qr1 = qr0 + 8 * DIM;
        #pragma unroll
        for (int j = 0; j < 4; j++) {
            aQ[rg][j][0] = *(const uint32_t*)(qr0 + 16 * j + 2 * lc);
            aQ[rg][j][1] = *(const uint32_t*)(qr1 + 16 * j + 2 * lc);
            aQ[rg][j][2] = *(const uint32_t*)(qr0 + 16 * j + 8 + 2 * lc);
            aQ[rg][j][3] = *(const uint32_t*)(qr1 + 16 * j + 8 + 2 * lc);
        }
    }

    const __half* gK  = qk + base;
    const __half* gVt = vt + base;

    // ---- init ones/zero rows (V rows 64..71) in BOTH buffers ----
    #pragma unroll
    for (int i = 0; i < 3; i++) {
        int idx = tid + i * 128;
        if (idx < 288) {
            uint32_t v = (idx < 36) ? 0x3C003C00u : 0u;   // row 64 = 1.0 fp16
            sts32(smbase + KT_BYTES + 64 * KV_ROWB + idx * 4, v);
            sts32(smbase + BUF_BYTES + KT_BYTES + 64 * KV_ROWB + idx * 4, v);
        }
    }

    // ---- stage tile 0 ----
    #pragma unroll
    for (int i = 0; i < 4; i++) {
        int id = tid + i * 128;
        int n = id >> 3, cseg = id & 7;
        CP_ASYNC16(smbase + n * KV_ROWB + cseg * 16, gK + n * DIM + cseg * 8);
        CP_ASYNC16(smbase + KT_BYTES + n * KV_ROWB + cseg * 16,
                   gVt + (size_t)n * NSEQ + cseg * 8);
    }
    CP_COMMIT();

    float o[2][9][4];
    #pragma unroll
    for (int rg = 0; rg < 2; rg++)
        #pragma unroll
        for (int b = 0; b < 9; b++)
            #pragma unroll
            for (int k = 0; k < 4; k++) o[rg][b][k] = 0.0f;

    const uint32_t lrow = (uint32_t)(lane & 7) * KV_ROWB;
    const uint32_t kseg = (uint32_t)(lane >> 3) * 16;

    for (int it = 0; it < NSEQ / 64; ++it) {
        CP_WAIT0();
        __syncthreads();
        const uint32_t smK = smbase + (uint32_t)(it & 1) * BUF_BYTES;
        const uint32_t smV = smK + KT_BYTES;

        if (it + 1 < NSEQ / 64) {
            const __half* nK  = gK  + (it + 1) * 64 * DIM;
            const __half* nVt = gVt + (it + 1) * 64;
            uint32_t dbuf = smbase + (uint32_t)((it + 1) & 1) * BUF_BYTES;
            #pragma unroll
            for (int i = 0; i < 4; i++) {
                int id = tid + i * 128;
                int n = id >> 3, cseg = id & 7;
                CP_ASYNC16(dbuf + n * KV_ROWB + cseg * 16, nK + n * DIM + cseg * 8);
                CP_ASYNC16(dbuf + KT_BYTES + n * KV_ROWB + cseg * 16,
                           nVt + (size_t)n * NSEQ + cseg * 8);
            }
            CP_COMMIT();
        }

        uint32_t aP[2][4][4];

        // ---- phase 1: S b0..b3 -> aP[0], aP[1] ----
        #pragma unroll
        for (int b = 0; b < 4; b++) S_BLOCK(b)

        // ---- phase 2: O(j=0,1) over 9 d-blocks, interleaved with S b4..b7 ----
        #pragma unroll
        for (int b = 0; b < 9; b++) {
            uint32_t vb = smV + (uint32_t)b * (8 * KV_ROWB) + lrow + kseg;
            uint32_t f0[4];
            ldsm_x4(f0, vb);
            #pragma unroll
            for (int rg = 0; rg < 2; rg++)
                mma_f32a2(o[rg][b], aP[rg][0], aP[rg][1], f0);
            if (b < 4) S_BLOCK(b + 4)
        }

        // ---- phase 3: O(j=2,3) over 9 d-blocks ----
        #pragma unroll
        for (int b = 0; b < 9; b++) {
            uint32_t vb = smV + (uint32_t)b * (8 * KV_ROWB) + lrow + kseg + 64;
            uint32_t f1[4];
            ldsm_x4(f1, vb);
            #pragma unroll
            for (int rg = 0; rg < 2; rg++)
                mma_f32a2(o[rg][b], aP[rg][2], aP[rg][3], f1);
        }
    }

    __syncthreads();   // all warps done with K/V smem

    // ---- normalize by l (ones-column, d=64 -> lc==0 regs 0/2), av -> smem ----
    #pragma unroll
    for (int rg = 0; rg < 2; rg++) {
        const float lA = __shfl_sync(0xFFFFFFFFu, o[rg][8][0], lane & ~3);
        const float lB = __shfl_sync(0xFFFFFFFFu, o[rg][8][2], lane & ~3);
        const float invl0 = 1.0f / lA;
        const float invl1 = 1.0f / lB;
        int row0 = warp * 32 + rg * 16 + lr;
        uint32_t a0 = smbase + (uint32_t)(row0 * AV_STRIDE + lc) * 4;
        uint32_t a1 = smbase + (uint32_t)((row0 + 8) * AV_STRIDE + lc) * 4;
        #pragma unroll
        for (int b = 0; b < 8; b++) {
            sts32(a0 + b * 16, packh(o[rg][b][0] * invl0, o[rg][b][1] * invl0));
            sts32(a1 + b * 16, packh(o[rg][b][2] * invl1, o[rg][b][3] * invl1));
        }
    }
    // stage W (64x64 f32 = 16KB)
    #pragma unroll
    for (int i = 0; i < 8; i++) {
        int idx = tid + i * 128;
        CP_ASYNC16(smbase + W_SM_OFF + idx * 16, (const float4*)W + idx);
    }
    CP_COMMIT();
    CP_WAIT0();
    __syncthreads();

    // ---- epilogue: y = relu(av @ W^T + x), one row per thread ----
    {
        const int rowc = warp * 32 + lane;
        float avf[64];
        uint32_t abase = smbase + (uint32_t)(rowc * AV_STRIDE) * 4;
        #pragma unroll
        for (int i = 0; i < 32; i++) {
            uint32_t u = lds32(abase + i * 4);
            __half2 h = *reinterpret_cast<__half2*>(&u);
            float2 f = __half22float2(h);
            avf[2 * i] = f.x;
            avf[2 * i + 1] = f.y;
        }
        const int grow = blockIdx.x * 128 + rowc;
        const float4* xr4 = (const float4*)(x + base + (size_t)grow * DIM);
        float4* out4 = (float4*)(out + base + (size_t)grow * DIM);
        #pragma unroll 1
        for (int eb = 0; eb < 16; eb++) {
            float r[4];
            #pragma unroll
            for (int k = 0; k < 4; k++) {
                int e = eb * 4 + k;
                uint32_t wbase = smbase + W_SM_OFF + (uint32_t)e * 256;
                float4 acc = make_float4(0.f, 0.f, 0.f, 0.f);
                #pragma unroll
                for (int i = 0; i < 16; i++) {
                    float4 wv = lds128(wbase + i * 16);
                    acc.x = fmaf(avf[4 * i + 0], wv.x, acc.x);
                    acc.y = fmaf(avf[4 * i + 1], wv.y, acc.y);
                    acc.z = fmaf(avf[4 * i + 2], wv.z, acc.z);
                    acc.w = fmaf(avf[4 * i + 3], wv.w, acc.w);
                }
                r[k] = (acc.x + acc.y) + (acc.z + acc.w);
            }
            float4 xr = xr4[eb];
            float4 res;
            res.x = fmaxf(r[0] + xr.x, 0.0f);
            res.y = fmaxf(r[1] + xr.y, 0.0f);
            res.z = fmaxf(r[2] + xr.z, 0.0f);
            res.w = fmaxf(r[3] + xr.w, 0.0f);
            out4[eb] = res;
        }
    }
}

// ---------------------------------------------------------------------------
// Driver (graph-capturable)
// ---------------------------------------------------------------------------
extern "C" void kernel_launch(void* const* d_in, const int* in_sizes, int n_in,
                              void* d_out, int out_size) {
    const float* x      = (const float*)d_in[0];
    const float* W1     = (const float*)d_in[1];
    const float* W2     = (const float*)d_in[2];
    const float* alpha1 = (const float*)d_in[3];
    const float* alpha2 = (const float*)d_in[4];
    float* out = (float*)d_out;

    __half* qk;  cudaGetSymbolAddress((void**)&qk,  g_qk);
    __half* vtp; cudaGetSymbolAddress((void**)&vtp, g_vt);
    float* tmp;  cudaGetSymbolAddress((void**)&tmp, g_tmp);

    dim3 pgrid(NSEQ / 64, BH);
    dim3 agrid(NSEQ / 128, BH);

    prep_kernel<<<pgrid, 256>>>(x, qk, vtp);
    attn_mma_kernel<<<agrid, 128>>>(x, qk, vtp, W1, alpha1, tmp);
    prep_kernel<<<pgrid, 256>>>(tmp, qk, vtp);
    attn_mma_kernel<<<agrid, 128>>>(tmp, qk, vtp, W2, alpha2, out);
}

// round 10
// speedup vs baseline: 1.0842x; 1.0487x over previous
#include <cuda_runtime.h>
#include <cuda_fp16.h>
#include <cstdint>

#define BH   16
#define NSEQ 4096
#define DIM  64
#define ROWS (BH * NSEQ)
#define ELEMS (ROWS * DIM)

// Scratch (__device__ globals per allocation-free rule)
__device__ __half g_qk[ELEMS];   // normalized x, fp16, [bh][n][d]
__device__ __half g_vt[ELEMS];   // x transposed,  fp16, [bh][d][n]
__device__ float  g_tmp[ELEMS];  // block-1 output

// ---------------------------------------------------------------------------
// helpers
// ---------------------------------------------------------------------------
__device__ __forceinline__ uint32_t smem_u32(const void* p) {
    uint32_t a;
    asm("{ .reg .u64 t; cvta.to.shared.u64 t, %1; cvt.u32.u64 %0, t; }" : "=r"(a) : "l"(p));
    return a;
}
__device__ __forceinline__ uint32_t lds32(uint32_t a) {
    uint32_t v;
    asm volatile("ld.shared.b32 %0, [%1];" : "=r"(v) : "r"(a));
    return v;
}
__device__ __forceinline__ void sts32(uint32_t a, uint32_t v) {
    asm volatile("st.shared.b32 [%0], %1;" :: "r"(a), "r"(v));
}
__device__ __forceinline__ float4 lds128(uint32_t a) {
    float4 v;
    asm volatile("ld.shared.v4.f32 {%0,%1,%2,%3}, [%4];"
                 : "=f"(v.x), "=f"(v.y), "=f"(v.z), "=f"(v.w) : "r"(a));
    return v;
}
__device__ __forceinline__ void ldsm_x4(uint32_t r[4], uint32_t addr) {
    asm volatile("ldmatrix.sync.aligned.m8n8.x4.shared.b16 {%0,%1,%2,%3}, [%4];"
                 : "=r"(r[0]), "=r"(r[1]), "=r"(r[2]), "=r"(r[3]) : "r"(addr));
}
__device__ __forceinline__ uint32_t packh(float lo, float hi) {
    uint32_t r;
    asm("cvt.rn.f16x2.f32 %0, %1, %2;" : "=r"(r) : "f"(hi), "f"(lo));
    return r;
}
__device__ __forceinline__ uint32_t hfma2(uint32_t a, uint32_t b, uint32_t c) {
    uint32_t d;
    asm("fma.rn.f16x2 %0, %1, %2, %3;" : "=r"(d) : "r"(a), "r"(b), "r"(c));
    return d;
}
__device__ __forceinline__ uint32_t hmul2(uint32_t a, uint32_t b) {
    uint32_t d;
    asm("mul.rn.f16x2 %0, %1, %2;" : "=r"(d) : "r"(a), "r"(b));
    return d;
}
__device__ __forceinline__ uint32_t ex2h2(uint32_t y) {
    uint32_t r;
    asm("ex2.approx.f16x2 %0, %1;" : "=r"(r) : "r"(y));
    return r;
}
// f16 inputs, f16 accumulate (2x rate): S-GEMM and O data blocks
__device__ __forceinline__ void mma_f16a(uint32_t c[2], const uint32_t a[4],
                                         uint32_t b0, uint32_t b1) {
    asm("mma.sync.aligned.m16n8k16.row.col.f16.f16.f16.f16 "
        "{%0,%1},{%2,%3,%4,%5},{%6,%7},{%0,%1};"
        : "+r"(c[0]), "+r"(c[1])
        : "r"(a[0]), "r"(a[1]), "r"(a[2]), "r"(a[3]), "r"(b0), "r"(b1));
}
// f16 inputs, f32 accumulate: l ones-block only
__device__ __forceinline__ void mma_f32a(float c[4], const uint32_t a[4],
                                         uint32_t b0, uint32_t b1) {
    asm("mma.sync.aligned.m16n8k16.row.col.f32.f16.f16.f32 "
        "{%0,%1,%2,%3},{%4,%5,%6,%7},{%8,%9},{%0,%1,%2,%3};"
        : "+f"(c[0]), "+f"(c[1]), "+f"(c[2]), "+f"(c[3])
        : "r"(a[0]), "r"(a[1]), "r"(a[2]), "r"(a[3]), "r"(b0), "r"(b1));
}
#define CP_ASYNC16(dst, src) \
    asm volatile("cp.async.cg.shared.global [%0], [%1], 16;" :: "r"(dst), "l"(src))
#define CP_COMMIT() asm volatile("cp.async.commit_group;" ::: "memory")
#define CP_WAIT0()  asm volatile("cp.async.wait_group 0;" ::: "memory")

// ---------------------------------------------------------------------------
// Fused prep: L2-normalize rows -> qn (fp16 [n][d]); transpose -> vt ([d][n])
// ---------------------------------------------------------------------------
__global__ void __launch_bounds__(256)
prep_kernel(const float* __restrict__ x,
            __half* __restrict__ qn, __half* __restrict__ vt) {
    __shared__ float tile[64][65];
    __shared__ float sinv[64];
    const int tid = threadIdx.x;
    const int bh = blockIdx.y;
    const int n0 = blockIdx.x * 64;
    const float* xb = x + ((size_t)bh * NSEQ + n0) * DIM;
    #pragma unroll
    for (int i = 0; i < 16; i++) {
        int idx = tid + i * 256;
        tile[idx >> 6][idx & 63] = xb[idx];
    }
    __syncthreads();
    {
        int n = tid >> 2, p = tid & 3;
        float ss = 0.0f;
        #pragma unroll
        for (int k = 0; k < 16; k++) {
            float v = tile[n][p * 16 + k];
            ss = fmaf(v, v, ss);
        }
        ss += __shfl_xor_sync(0xFFFFFFFFu, ss, 1);
        ss += __shfl_xor_sync(0xFFFFFFFFu, ss, 2);
        if (p == 0) sinv[n] = 1.0f / fmaxf(sqrtf(ss), 1e-12f);
    }
    __syncthreads();
    __half* qb = qn + ((size_t)bh * NSEQ + n0) * DIM;
    __half* vb = vt + (size_t)bh * NSEQ * DIM + n0;
    #pragma unroll
    for (int i = 0; i < 16; i++) {
        int idx = tid + i * 256;
        int n = idx >> 6, d = idx & 63;
        qb[idx] = __float2half(tile[n][d] * sinv[n]);
    }
    #pragma unroll
    for (int i = 0; i < 16; i++) {
        int idx = tid + i * 256;
        int d = idx >> 6, n = idx & 63;
        vb[(size_t)d * NSEQ + n] = __float2half(tile[n][d]);
    }
}

// ---------------------------------------------------------------------------
// Flash-attention block on mma.sync, fp16.
// S-GEMM AND O data blocks in f16-accum (2x MMA rate); only the l
// ones-column block keeps f32 accumulation. Registers ~145 -> 3 CTAs/SM
// (12 warps) for latency hiding. 4 warps, 32 q rows/warp, double-buffered.
// ---------------------------------------------------------------------------
#define KV_ROWB 144
#define KT_BYTES (64 * KV_ROWB)         // 9216
#define VT_BYTES (72 * KV_ROWB)         // 10368 (64 data + ones + zeros)
#define BUF_BYTES (KT_BYTES + VT_BYTES) // 19584
#define AV_STRIDE 34                     // u32 per row (68 fp16)
#define W_SM_OFF 17408                   // av: 128*34*4, then W (16KB)

__global__ void __launch_bounds__(128, 3)
attn_mma_kernel(const float* __restrict__ x,
                const __half* __restrict__ qk,
                const __half* __restrict__ vt,
                const float* __restrict__ W,
                const float* __restrict__ alpha_p,
                float* __restrict__ out) {
    __shared__ __align__(16) uint8_t smem_raw[2 * BUF_BYTES];

    const int tid  = threadIdx.x;
    const int warp = tid >> 5;
    const int lane = tid & 31;
    const int lr   = lane >> 2;
    const int lc   = lane & 3;
    const uint32_t smbase = smem_u32(smem_raw);

    const size_t base = (size_t)blockIdx.y * NSEQ * DIM;
    const int q0 = blockIdx.x * 128 + warp * 32;
    const float cf = 1.4426950408889634f / fmaxf(alpha_p[0], 0.01f);
    const uint32_t cc  = packh(cf, cf);
    const uint32_t ncc = packh(-cf, -cf);

    // ---- Q A-fragments: 2 row-groups x 4 k-chunks ----
    uint32_t aQ[2][4][4];
    #pragma unroll
    for (int rg = 0; rg < 2; rg++) {
        const __half* qr0 = qk + base + (size_t)(q0 + rg * 16 + lr) * DIM;
        const __half* qr1 = qr0 + 8 * DIM;
        #pragma unroll
        for (int j = 0; j < 4; j++) {
            aQ[rg][j][0] = *(const uint32_t*)(qr0 + 16 * j + 2 * lc);
            aQ[rg][j][1] = *(const uint32_t*)(qr1 + 16 * j + 2 * lc);
            aQ[rg][j][2] = *(const uint32_t*)(qr0 + 16 * j + 8 + 2 * lc);
            aQ[rg][j][3] = *(const uint32_t*)(qr1 + 16 * j + 8 + 2 * lc);
        }
    }

    const __half* gK  = qk + base;
    const __half* gVt = vt + base;

    // ---- init ones/zero rows (V rows 64..71) in BOTH buffers ----
    #pragma unroll
    for (int i = 0; i < 3; i++) {
        int idx = tid + i * 128;
        if (idx < 288) {
            uint32_t v = (idx < 36) ? 0x3C003C00u : 0u;   // row 64 = 1.0 fp16
            sts32(smbase + KT_BYTES + 64 * KV_ROWB + idx * 4, v);
            sts32(smbase + BUF_BYTES + KT_BYTES + 64 * KV_ROWB + idx * 4, v);
        }
    }

    // ---- stage tile 0 ----
    #pragma unroll
    for (int i = 0; i < 4; i++) {
        int id = tid + i * 128;
        int n = id >> 3, cseg = id & 7;
        CP_ASYNC16(smbase + n * KV_ROWB + cseg * 16, gK + n * DIM + cseg * 8);
        CP_ASYNC16(smbase + KT_BYTES + n * KV_ROWB + cseg * 16,
                   gVt + (size_t)n * NSEQ + cseg * 8);
    }
    CP_COMMIT();

    uint32_t o16[2][8][2];      // f16x2 O accumulators (rows lr / lr+8)
    float    ol[2][4];          // f32 l accumulators (ones block)
    #pragma unroll
    for (int rg = 0; rg < 2; rg++) {
        #pragma unroll
        for (int b = 0; b < 8; b++) { o16[rg][b][0] = 0u; o16[rg][b][1] = 0u; }
        #pragma unroll
        for (int k = 0; k < 4; k++) ol[rg][k] = 0.0f;
    }

    const uint32_t lrow = (uint32_t)(lane & 7) * KV_ROWB;
    const uint32_t kseg = (uint32_t)(lane >> 3) * 16;

    for (int it = 0; it < NSEQ / 64; ++it) {
        CP_WAIT0();
        __syncthreads();
        const uint32_t smK = smbase + (uint32_t)(it & 1) * BUF_BYTES;
        const uint32_t smV = smK + KT_BYTES;

        if (it + 1 < NSEQ / 64) {
            const __half* nK  = gK  + (it + 1) * 64 * DIM;
            const __half* nVt = gVt + (it + 1) * 64;
            uint32_t dbuf = smbase + (uint32_t)((it + 1) & 1) * BUF_BYTES;
            #pragma unroll
            for (int i = 0; i < 4; i++) {
                int id = tid + i * 128;
                int n = id >> 3, cseg = id & 7;
                CP_ASYNC16(dbuf + n * KV_ROWB + cseg * 16, nK + n * DIM + cseg * 8);
                CP_ASYNC16(dbuf + KT_BYTES + n * KV_ROWB + cseg * 16,
                           nVt + (size_t)n * NSEQ + cseg * 8);
            }
            CP_COMMIT();
        }

        // ---- S = Q@K^T (f16 accum); softmax -> aP directly ----
        uint32_t aP[2][4][4];
        #pragma unroll
        for (int b = 0; b < 8; b++) {
            uint32_t abase = smK + (uint32_t)b * (8 * KV_ROWB) + lrow + kseg;
            uint32_t f0[4], f1[4];
            ldsm_x4(f0, abase);
            ldsm_x4(f1, abase + 64);
            #pragma unroll
            for (int rg = 0; rg < 2; rg++) {
                uint32_t s[2];
                s[0] = 0u; s[1] = 0u;
                mma_f16a(s, aQ[rg][0], f0[0], f0[1]);
                mma_f16a(s, aQ[rg][1], f0[2], f0[3]);
                mma_f16a(s, aQ[rg][2], f1[0], f1[1]);
                mma_f16a(s, aQ[rg][3], f1[2], f1[3]);
                uint32_t pa = ex2h2(hfma2(s[0], cc, ncc));
                uint32_t pb = ex2h2(hfma2(s[1], cc, ncc));
                int j = b >> 1;
                if ((b & 1) == 0) { aP[rg][j][0] = pa; aP[rg][j][1] = pb; }
                else              { aP[rg][j][2] = pa; aP[rg][j][3] = pb; }
            }
        }

        // ---- O += P @ V : data blocks f16-accum (2x), l block f32-accum ----
        #pragma unroll
        for (int b = 0; b < 9; b++) {
            uint32_t abase = smV + (uint32_t)b * (8 * KV_ROWB) + lrow + kseg;
            uint32_t f0[4], f1[4];
            ldsm_x4(f0, abase);
            ldsm_x4(f1, abase + 64);
            if (b < 8) {
                #pragma unroll
                for (int rg = 0; rg < 2; rg++) {
                    mma_f16a(o16[rg][b], aP[rg][0], f0[0], f0[1]);
                    mma_f16a(o16[rg][b], aP[rg][1], f0[2], f0[3]);
                    mma_f16a(o16[rg][b], aP[rg][2], f1[0], f1[1]);
                    mma_f16a(o16[rg][b], aP[rg][3], f1[2], f1[3]);
                }
            } else {
                #pragma unroll
                for (int rg = 0; rg < 2; rg++) {
                    mma_f32a(ol[rg], aP[rg][0], f0[0], f0[1]);
                    mma_f32a(ol[rg], aP[rg][1], f0[2], f0[3]);
                    mma_f32a(ol[rg], aP[rg][2], f1[0], f1[1]);
                    mma_f32a(ol[rg], aP[rg][3], f1[2], f1[3]);
                }
            }
        }
    }

    __syncthreads();   // all warps done with K/V smem

    // ---- normalize by l (f32 from ones block, col 64 -> lc==0 regs 0/2) ----
    #pragma unroll
    for (int rg = 0; rg < 2; rg++) {
        const float lA = __shfl_sync(0xFFFFFFFFu, ol[rg][0], lane & ~3);
        const float lB = __shfl_sync(0xFFFFFFFFu, ol[rg][2], lane & ~3);
        const float i0f = 1.0f / lA;
        const float i1f = 1.0f / lB;
        const uint32_t i0 = packh(i0f, i0f);
        const uint32_t i1 = packh(i1f, i1f);
        int row0 = warp * 32 + rg * 16 + lr;
        uint32_t a0 = smbase + (uint32_t)(row0 * AV_STRIDE + lc) * 4;
        uint32_t a1 = smbase + (uint32_t)((row0 + 8) * AV_STRIDE + lc) * 4;
        #pragma unroll
        for (int b = 0; b < 8; b++) {
            sts32(a0 + b * 16, hmul2(o16[rg][b][0], i0));
            sts32(a1 + b * 16, hmul2(o16[rg][b][1], i1));
        }
    }
    // stage W (64x64 f32 = 16KB)
    #pragma unroll
    for (int i = 0; i < 8; i++) {
        int idx = tid + i * 128;
        CP_ASYNC16(smbase + W_SM_OFF + idx * 16, (const float4*)W + idx);
    }
    CP_COMMIT();
    CP_WAIT0();
    __syncthreads();

    // ---- epilogue: y = relu(av @ W^T + x), one row per thread ----
    {
        const int rowc = warp * 32 + lane;
        float avf[64];
        uint32_t abase = smbase + (uint32_t)(rowc * AV_STRIDE) * 4;
        #pragma unroll
        for (int i = 0; i < 32; i++) {
            uint32_t u = lds32(abase + i * 4);
            __half2 h = *reinterpret_cast<__half2*>(&u);
            float2 f = __half22float2(h);
            avf[2 * i] = f.x;
            avf[2 * i + 1] = f.y;
        }
        const int grow = blockIdx.x * 128 + rowc;
        const float4* xr4 = (const float4*)(x + base + (size_t)grow * DIM);
        float4* out4 = (float4*)(out + base + (size_t)grow * DIM);
        #pragma unroll 1
        for (int eb = 0; eb < 16; eb++) {
            float r[4];
            #pragma unroll
            for (int k = 0; k < 4; k++) {
                int e = eb * 4 + k;
                uint32_t wbase = smbase + W_SM_OFF + (uint32_t)e * 256;
                float4 acc = make_float4(0.f, 0.f, 0.f, 0.f);
                #pragma unroll
                for (int i = 0; i < 16; i++) {
                    float4 wv = lds128(wbase + i * 16);
                    acc.x = fmaf(avf[4 * i + 0], wv.x, acc.x);
                    acc.y = fmaf(avf[4 * i + 1], wv.y, acc.y);
                    acc.z = fmaf(avf[4 * i + 2], wv.z, acc.z);
                    acc.w = fmaf(avf[4 * i + 3], wv.w, acc.w);
                }
                r[k] = (acc.x + acc.y) + (acc.z + acc.w);
            }
            float4 xr = xr4[eb];
            float4 res;
            res.x = fmaxf(r[0] + xr.x, 0.0f);
            res.y = fmaxf(r[1] + xr.y, 0.0f);
            res.z = fmaxf(r[2] + xr.z, 0.0f);
            res.w = fmaxf(r[3] + xr.w, 0.0f);
            out4[eb] = res;
        }
    }
}

// ---------------------------------------------------------------------------
// Driver (graph-capturable)
// ---------------------------------------------------------------------------
extern "C" void kernel_launch(void* const* d_in, const int* in_sizes, int n_in,
                              void* d_out, int out_size) {
    const float* x      = (const float*)d_in[0];
    const float* W1     = (const float*)d_in[1];
    const float* W2     = (const float*)d_in[2];
    const float* alpha1 = (const float*)d_in[3];
    const float* alpha2 = (const float*)d_in[4];
    float* out = (float*)d_out;

    __half* qk;  cudaGetSymbolAddress((void**)&qk,  g_qk);
    __half* vtp; cudaGetSymbolAddress((void**)&vtp, g_vt);
    float* tmp;  cudaGetSymbolAddress((void**)&tmp, g_tmp);

    dim3 pgrid(NSEQ / 64, BH);
    dim3 agrid(NSEQ / 128, BH);

    prep_kernel<<<pgrid, 256>>>(x, qk, vtp);
    attn_mma_kernel<<<agrid, 128>>>(x, qk, vtp, W1, alpha1, tmp);
    prep_kernel<<<pgrid, 256>>>(tmp, qk, vtp);
    attn_mma_kernel<<<agrid, 128>>>(tmp, qk, vtp, W2, alpha2, out);
}